// round 9
// baseline (speedup 1.0000x reference)
#include <cuda_runtime.h>
#include <math.h>

// Problem constants
#define BB   4
#define SS   2048
#define DM   1024
#define NH   16
#define HD   64
#define FF   4096
#define MR   (BB*SS)        // 8192 rows
#define QKVD (3*DM)         // 3072

// ---------------------------------------------------------------------------
// Scratch (static __device__ arrays: allocation-free per harness rules)
// ---------------------------------------------------------------------------
__device__ float g_wqkv[DM * QKVD];   // packed [K=1024][3072] weights
__device__ float g_bqkv[QKVD];
__device__ float g_qkv [MR * QKVD];   // fused QKV output
__device__ float g_ctx [MR * DM];
__device__ float g_attn[MR * DM];
__device__ float g_x1  [MR * DM];
__device__ float g_hid [MR * FF];
__device__ float g_ffn [MR * DM];

// ---------------------------------------------------------------------------
// Pack Wq|Wk|Wv into one [1024 x 3072] matrix (and biases). Trivial traffic.
// ---------------------------------------------------------------------------
__global__ void pack_qkv(const float* __restrict__ Wq, const float* __restrict__ Wk,
                         const float* __restrict__ Wv, const float* __restrict__ bq,
                         const float* __restrict__ bk, const float* __restrict__ bv,
                         float* __restrict__ W, float* __restrict__ bias)
{
    int idx = blockIdx.x * blockDim.x + threadIdx.x;
    if (idx < DM * DM) {
        int r = idx >> 10, c = idx & 1023;
        size_t o = (size_t)r * QKVD + c;
        W[o]          = Wq[idx];
        W[o + DM]     = Wk[idx];
        W[o + 2 * DM] = Wv[idx];
    }
    if (idx < DM) {
        bias[idx]          = bq[idx];
        bias[idx + DM]     = bk[idx];
        bias[idx + 2 * DM] = bv[idx];
    }
}

// fast tanh-GELU: tanh(y) = 1 - 2/(exp(2y)+1), MUFU-based
__device__ __forceinline__ float gelu_fast(float t)
{
    float y = 0.7978845608f * (t + 0.044715f * t * t * t);
    float th = 1.f - __fdividef(2.f, __expf(2.f * y) + 1.f);
    return 0.5f * t * (1.f + th);
}

// ---------------------------------------------------------------------------
// SGEMM: C[M,N] = act(A[M,K] @ B[K,N] + bias[N])
// 128x128 block tile, BK=16, 256 threads, 8x8 per thread.
// Double-buffered smem: ONE __syncthreads per K-tile.
// ACT: 0 = none, 1 = tanh-GELU
// ---------------------------------------------------------------------------
template<int ACT>
__global__ __launch_bounds__(256)
void sgemm_bias(const float* __restrict__ A, const float* __restrict__ B,
                const float* __restrict__ bias, float* __restrict__ C,
                int M, int N, int K)
{
    __shared__ __align__(16) float As[2][16][132];
    __shared__ __align__(16) float Bs[2][16][132];

    const int tid = threadIdx.x;
    const int bm  = blockIdx.y * 128;
    const int bn  = blockIdx.x * 128;
    const int tx  = tid & 15;          // 0..15  -> col group
    const int ty  = tid >> 4;          // 0..15  -> row group

    const int arow = tid >> 1;         // 0..127
    const int acol = (tid & 1) * 8;    // 0 or 8 (two float4 each)
    const int brow = tid >> 5;         // 0..7  (and brow+8)
    const int bcol = (tid & 31) * 4;   // 0..124

    const float* Ap  = A + (size_t)(bm + arow) * K + acol;
    const float* Bp  = B + (size_t)brow * N + bn + bcol;   // rows brow, brow+8

    float acc[8][8];
#pragma unroll
    for (int i = 0; i < 8; i++)
#pragma unroll
        for (int j = 0; j < 8; j++) acc[i][j] = 0.f;

    // load tile 0 into buffer 0
    float4 av0 = *(const float4*)Ap;
    float4 av1 = *(const float4*)(Ap + 4);
    float4 bv0 = *(const float4*)Bp;
    float4 bv1 = *(const float4*)(Bp + (size_t)8 * N);
    As[0][acol + 0][arow] = av0.x;  As[0][acol + 1][arow] = av0.y;
    As[0][acol + 2][arow] = av0.z;  As[0][acol + 3][arow] = av0.w;
    As[0][acol + 4][arow] = av1.x;  As[0][acol + 5][arow] = av1.y;
    As[0][acol + 6][arow] = av1.z;  As[0][acol + 7][arow] = av1.w;
    *(float4*)&Bs[0][brow][bcol]     = bv0;
    *(float4*)&Bs[0][brow + 8][bcol] = bv1;
    __syncthreads();

    int buf = 0;
    for (int k0 = 0; k0 < K; k0 += 16) {
        const bool has_next = (k0 + 16 < K);
        if (has_next) {          // prefetch next tile into registers
            Ap += 16;
            Bp += (size_t)16 * N;
            av0 = *(const float4*)Ap;
            av1 = *(const float4*)(Ap + 4);
            bv0 = *(const float4*)Bp;
            bv1 = *(const float4*)(Bp + (size_t)8 * N);
        }

#pragma unroll
        for (int kk = 0; kk < 16; kk++) {
            float a[8], b[8];
            *(float4*)(a)     = *(const float4*)&As[buf][kk][ty * 8];
            *(float4*)(a + 4) = *(const float4*)&As[buf][kk][ty * 8 + 4];
            *(float4*)(b)     = *(const float4*)&Bs[buf][kk][tx * 8];
            *(float4*)(b + 4) = *(const float4*)&Bs[buf][kk][tx * 8 + 4];
#pragma unroll
            for (int i = 0; i < 8; i++)
#pragma unroll
                for (int j = 0; j < 8; j++)
                    acc[i][j] += a[i] * b[j];
        }

        if (has_next) {          // store prefetched tile to the idle buffer
            const int nb = buf ^ 1;
            As[nb][acol + 0][arow] = av0.x;  As[nb][acol + 1][arow] = av0.y;
            As[nb][acol + 2][arow] = av0.z;  As[nb][acol + 3][arow] = av0.w;
            As[nb][acol + 4][arow] = av1.x;  As[nb][acol + 5][arow] = av1.y;
            As[nb][acol + 6][arow] = av1.z;  As[nb][acol + 7][arow] = av1.w;
            *(float4*)&Bs[nb][brow][bcol]     = bv0;
            *(float4*)&Bs[nb][brow + 8][bcol] = bv1;
            __syncthreads();
            buf = nb;
        }
    }

    // epilogue: bias (+ GELU), vectorized stores
    float4 bia0 = *(const float4*)&bias[bn + tx * 8];
    float4 bia1 = *(const float4*)&bias[bn + tx * 8 + 4];
#pragma unroll
    for (int i = 0; i < 8; i++) {
        const int row = bm + ty * 8 + i;
        float* Crow = C + (size_t)row * N + bn + tx * 8;
        float u[8];
        u[0] = acc[i][0] + bia0.x; u[1] = acc[i][1] + bia0.y;
        u[2] = acc[i][2] + bia0.z; u[3] = acc[i][3] + bia0.w;
        u[4] = acc[i][4] + bia1.x; u[5] = acc[i][5] + bia1.y;
        u[6] = acc[i][6] + bia1.z; u[7] = acc[i][7] + bia1.w;
        if (ACT == 1) {
#pragma unroll
            for (int j = 0; j < 8; j++) u[j] = gelu_fast(u[j]);
        }
        *(float4*)(Crow)     = make_float4(u[0], u[1], u[2], u[3]);
        *(float4*)(Crow + 4) = make_float4(u[4], u[5], u[6], u[7]);
    }
}

// ---------------------------------------------------------------------------
// Flash attention: per (b, h, q-tile of 64), streaming 32-key tiles.
// DOUBLE-BUFFERED K/V. K stored TRANSPOSED: Kt[d][row], row stride 36 floats
// (144B = 9*16B) so &Kt[d][sk] is 16B-aligned -> LDS.128 in score phase.
// Warp-level bank check (score reads): sk in {0,4..28} at fixed d covers all
// 32 banks exactly once; same-sk lanes broadcast -> conflict-free.
// Transpose STS is 4-way conflicted (bank = (4c+r)%32) - net win vs 16
// scalar LDS per chunk it removes.
// Barriers per iter: A (WAR on buf^1) / C (Ps + stores visible) / D (probs).
// ---------------------------------------------------------------------------
__global__ __launch_bounds__(256)
void attn_kernel(const float* __restrict__ QKV, const unsigned char* __restrict__ mask,
                 float* __restrict__ O)
{
    __shared__ __align__(16) float Qs[64][68];      // f4-aligned rows
    __shared__ __align__(16) float Kt[2][64][36];   // TRANSPOSED: [dim][row]
    __shared__ __align__(16) float Vs[2][32][68];
    __shared__ __align__(16) float Ps[64][36];

    const int tid = threadIdx.x;
    const int q0  = blockIdx.x * 64;
    const int h   = blockIdx.y;
    const int b   = blockIdx.z;

    const size_t rowb  = (size_t)b * SS;
    const size_t qbase = rowb * QKVD + (size_t)h * HD;
    const size_t kbase = qbase + DM;
    const size_t vbase = qbase + 2 * DM;
    const size_t obase = rowb * DM + (size_t)h * HD;
    const unsigned char* mb = mask + (size_t)b * SS * SS;

    // load Q tile (scaled by rsqrt(HD) = 0.125)
    for (int i = tid; i < 64 * 16; i += 256) {
        int r = i >> 4, c = (i & 15) << 2;
        float4 t = *(const float4*)&QKV[qbase + (size_t)(q0 + r) * QKVD + c];
        Qs[r][c]     = t.x * 0.125f;
        Qs[r][c + 1] = t.y * 0.125f;
        Qs[r][c + 2] = t.z * 0.125f;
        Qs[r][c + 3] = t.w * 0.125f;
    }

    // prologue: tile 0 into buffer 0 (K transposed on store)
    for (int p = 0; p < 8; p++) {
        int i = tid + 256 * p, r = i >> 6, c = i & 63;
        Kt[0][c][r] = QKV[kbase + (size_t)r * QKVD + c];
    }
    for (int p = 0; p < 2; p++) {
        int i = tid + 256 * p, r = i >> 4, c = (i & 15) << 2;
        *(float4*)&Vs[0][r][c] = *(const float4*)&QKV[vbase + (size_t)r * QKVD + c];
    }

    // score phase mapping: 2 rows x 4 cols per thread
    const int sq = (tid >> 3) << 1;   // 0,2,..,62
    const int sk = (tid & 7)  << 2;   // 0,4,..,28
    // softmax/acc mapping: 4 threads per row
    const int qi = tid >> 2;          // 0..63
    const int dg = (tid & 3) << 4;    // dim group of 16
    const int c0 = (tid & 3) << 3;    // softmax col group of 8

    float m_i = -1e30f, l_i = 0.f;
    float acc[16];
#pragma unroll
    for (int i = 0; i < 16; i++) acc[i] = 0.f;

    int buf = 0;
    for (int kt = 0; kt < SS; kt += 32) {
        const bool has_next = (kt + 32 < SS);

        // prefetch next K/V tile into registers (latency hidden by A + scores)
        float kreg[8];
        float4 vreg[2];
        if (has_next) {
#pragma unroll
            for (int p = 0; p < 8; p++) {
                int i = tid + 256 * p, r = i >> 6, c = i & 63;
                kreg[p] = QKV[kbase + (size_t)(kt + 32 + r) * QKVD + c];
            }
#pragma unroll
            for (int p = 0; p < 2; p++) {
                int i = tid + 256 * p, r = i >> 4, c = (i & 15) << 2;
                vreg[p] = *(const float4*)&QKV[vbase + (size_t)(kt + 32 + r) * QKVD + c];
            }
        }

        __syncthreads();   // A: prev readers of buf^1 done; current buf visible

        // scores: 2x4 dots of length 64; Q and K both via LDS.128
        float s00 = 0.f, s01 = 0.f, s02 = 0.f, s03 = 0.f;
        float s10 = 0.f, s11 = 0.f, s12 = 0.f, s13 = 0.f;
#pragma unroll
        for (int d = 0; d < 64; d += 4) {
            float qa[4], qb[4];
            float k0[4], k1[4], k2[4], k3[4];   // k_e[y] = K[sk+y][d+e]
            *(float4*)qa = *(const float4*)&Qs[sq][d];
            *(float4*)qb = *(const float4*)&Qs[sq + 1][d];
            *(float4*)k0 = *(const float4*)&Kt[buf][d + 0][sk];
            *(float4*)k1 = *(const float4*)&Kt[buf][d + 1][sk];
            *(float4*)k2 = *(const float4*)&Kt[buf][d + 2][sk];
            *(float4*)k3 = *(const float4*)&Kt[buf][d + 3][sk];
            s00 += qa[0]*k0[0] + qa[1]*k1[0] + qa[2]*k2[0] + qa[3]*k3[0];
            s01 += qa[0]*k0[1] + qa[1]*k1[1] + qa[2]*k2[1] + qa[3]*k3[1];
            s02 += qa[0]*k0[2] + qa[1]*k1[2] + qa[2]*k2[2] + qa[3]*k3[2];
            s03 += qa[0]*k0[3] + qa[1]*k1[3] + qa[2]*k2[3] + qa[3]*k3[3];
            s10 += qb[0]*k0[0] + qb[1]*k1[0] + qb[2]*k2[0] + qb[3]*k3[0];
            s11 += qb[0]*k0[1] + qb[1]*k1[1] + qb[2]*k2[1] + qb[3]*k3[1];
            s12 += qb[0]*k0[2] + qb[1]*k1[2] + qb[2]*k2[2] + qb[3]*k3[2];
            s13 += qb[0]*k0[3] + qb[1]*k1[3] + qb[2]*k2[3] + qb[3]*k3[3];
        }
        // mask (all-False in this problem's inputs; kept for robustness)
        {
            const unsigned char* m0 = mb + (size_t)(q0 + sq) * SS + kt + sk;
            const unsigned char* m1 = m0 + SS;
            if (m0[0]) s00 = -1e30f; if (m0[1]) s01 = -1e30f;
            if (m0[2]) s02 = -1e30f; if (m0[3]) s03 = -1e30f;
            if (m1[0]) s10 = -1e30f; if (m1[1]) s11 = -1e30f;
            if (m1[2]) s12 = -1e30f; if (m1[3]) s13 = -1e30f;
        }
        Ps[sq][sk] = s00; Ps[sq][sk + 1] = s01; Ps[sq][sk + 2] = s02; Ps[sq][sk + 3] = s03;
        Ps[sq + 1][sk] = s10; Ps[sq + 1][sk + 1] = s11;
        Ps[sq + 1][sk + 2] = s12; Ps[sq + 1][sk + 3] = s13;

        // store prefetched tile into the idle buffer (K transposed)
        if (has_next) {
            const int nb = buf ^ 1;
#pragma unroll
            for (int p = 0; p < 8; p++) {
                int i = tid + 256 * p, r = i >> 6, c = i & 63;
                Kt[nb][c][r] = kreg[p];
            }
#pragma unroll
            for (int p = 0; p < 2; p++) {
                int i = tid + 256 * p, r = i >> 4, c = (i & 15) << 2;
                *(float4*)&Vs[nb][r][c] = vreg[p];
            }
        }

        __syncthreads();   // C: Ps scores visible; buf^1 stores ordered

        // online softmax: 4 threads per row, 8 cols each
        float pv[8];
        float rmax = -1e30f;
#pragma unroll
        for (int j = 0; j < 8; j++) { pv[j] = Ps[qi][c0 + j]; rmax = fmaxf(rmax, pv[j]); }
        rmax = fmaxf(rmax, __shfl_xor_sync(0xffffffffu, rmax, 1));
        rmax = fmaxf(rmax, __shfl_xor_sync(0xffffffffu, rmax, 2));
        float m_new = fmaxf(m_i, rmax);
        float corr  = __expf(m_i - m_new);
        float psum  = 0.f;
#pragma unroll
        for (int j = 0; j < 8; j++) {
            pv[j] = __expf(pv[j] - m_new);
            psum += pv[j];
            Ps[qi][c0 + j] = pv[j];
        }
        psum += __shfl_xor_sync(0xffffffffu, psum, 1);
        psum += __shfl_xor_sync(0xffffffffu, psum, 2);
        l_i = l_i * corr + psum;
        m_i = m_new;
#pragma unroll
        for (int i = 0; i < 16; i++) acc[i] *= corr;

        __syncthreads();   // D: Ps probabilities visible to whole block

        // acc += P @ V   (thread owns (row qi, 16 dims dg..dg+15)); V via float4 LDS
#pragma unroll 8
        for (int j = 0; j < 32; j++) {
            float p = Ps[qi][j];
            float v0[4], v1[4], v2[4], v3[4];
            *(float4*)v0 = *(const float4*)&Vs[buf][j][dg];
            *(float4*)v1 = *(const float4*)&Vs[buf][j][dg + 4];
            *(float4*)v2 = *(const float4*)&Vs[buf][j][dg + 8];
            *(float4*)v3 = *(const float4*)&Vs[buf][j][dg + 12];
#pragma unroll
            for (int e = 0; e < 4; e++) {
                acc[e]      += p * v0[e];
                acc[4 + e]  += p * v1[e];
                acc[8 + e]  += p * v2[e];
                acc[12 + e] += p * v3[e];
            }
        }

        buf ^= 1;
    }

    const float inv = 1.f / l_i;
#pragma unroll
    for (int i = 0; i < 16; i++)
        O[obase + (size_t)(q0 + qi) * DM + dg + i] = acc[i] * inv;
}

// ---------------------------------------------------------------------------
// out = LayerNorm(A + B) * gamma + beta      (one block per 1024-wide row)
// ---------------------------------------------------------------------------
__global__ __launch_bounds__(256)
void add_ln_kernel(const float* __restrict__ A, const float* __restrict__ Bv,
                   const float* __restrict__ gam, const float* __restrict__ bet,
                   float* __restrict__ out)
{
    __shared__ float red[8];
    const int row = blockIdx.x;
    const int t = threadIdx.x;

    float4 av = ((const float4*)(A  + (size_t)row * DM))[t];
    float4 bv = ((const float4*)(Bv + (size_t)row * DM))[t];
    float v0 = av.x + bv.x, v1 = av.y + bv.y, v2 = av.z + bv.z, v3 = av.w + bv.w;

    float s = v0 + v1 + v2 + v3;
#pragma unroll
    for (int o = 16; o > 0; o >>= 1) s += __shfl_xor_sync(0xffffffffu, s, o);
    if ((t & 31) == 0) red[t >> 5] = s;
    __syncthreads();
    float mu = 0.f;
#pragma unroll
    for (int i = 0; i < 8; i++) mu += red[i];
    mu *= (1.f / 1024.f);
    __syncthreads();

    float d0 = v0 - mu, d1 = v1 - mu, d2 = v2 - mu, d3 = v3 - mu;
    float sv = d0 * d0 + d1 * d1 + d2 * d2 + d3 * d3;
#pragma unroll
    for (int o = 16; o > 0; o >>= 1) sv += __shfl_xor_sync(0xffffffffu, sv, o);
    if ((t & 31) == 0) red[t >> 5] = sv;
    __syncthreads();
    float var = 0.f;
#pragma unroll
    for (int i = 0; i < 8; i++) var += red[i];
    var *= (1.f / 1024.f);
    const float inv = rsqrtf(var + 1e-5f);

    float4 g4 = ((const float4*)gam)[t];
    float4 e4 = ((const float4*)bet)[t];
    float4 o4;
    o4.x = d0 * inv * g4.x + e4.x;
    o4.y = d1 * inv * g4.y + e4.y;
    o4.z = d2 * inv * g4.z + e4.z;
    o4.w = d3 * inv * g4.w + e4.w;
    ((float4*)(out + (size_t)row * DM))[t] = o4;
}

// ---------------------------------------------------------------------------
// Launch
// ---------------------------------------------------------------------------
extern "C" void kernel_launch(void* const* d_in, const int* in_sizes, int n_in,
                              void* d_out, int out_size)
{
    const float* x  = (const float*)d_in[0];
    const unsigned char* mask = (const unsigned char*)d_in[1];
    const float* Wq = (const float*)d_in[2];
    const float* bq = (const float*)d_in[3];
    const float* Wk = (const float*)d_in[4];
    const float* bk = (const float*)d_in[5];
    const float* Wv = (const float*)d_in[6];
    const float* bv = (const float*)d_in[7];
    const float* Wo = (const float*)d_in[8];
    const float* bo = (const float*)d_in[9];
    const float* g1 = (const float*)d_in[10];
    const float* be1= (const float*)d_in[11];
    const float* W1 = (const float*)d_in[12];
    const float* b1 = (const float*)d_in[13];
    const float* W2 = (const float*)d_in[14];
    const float* b2 = (const float*)d_in[15];
    const float* g2 = (const float*)d_in[16];
    const float* be2= (const float*)d_in[17];
    float* out = (float*)d_out;

    float *wqkv, *bqkv, *qkv, *ctx, *attn, *x1, *hid, *ffn;
    cudaGetSymbolAddress((void**)&wqkv, g_wqkv);
    cudaGetSymbolAddress((void**)&bqkv, g_bqkv);
    cudaGetSymbolAddress((void**)&qkv,  g_qkv);
    cudaGetSymbolAddress((void**)&ctx,  g_ctx);
    cudaGetSymbolAddress((void**)&attn, g_attn);
    cudaGetSymbolAddress((void**)&x1,   g_x1);
    cudaGetSymbolAddress((void**)&hid,  g_hid);
    cudaGetSymbolAddress((void**)&ffn,  g_ffn);

    // pack QKV weights, then one fused projection GEMM
    pack_qkv<<<(DM * DM + 255) / 256, 256>>>(Wq, Wk, Wv, bq, bk, bv, wqkv, bqkv);

    const dim3 gQKV(QKVD / 128, MR / 128);  // (24, 64)
    const dim3 gDM (DM   / 128, MR / 128);  // (8, 64)
    const dim3 gFF (FF   / 128, MR / 128);  // (32, 64)

    sgemm_bias<0><<<gQKV, 256>>>(x, wqkv, bqkv, qkv, MR, QKVD, DM);

    // attention
    attn_kernel<<<dim3(SS / 64, NH, BB), 256>>>(qkv, mask, ctx);

    // output projection
    sgemm_bias<0><<<gDM, 256>>>(ctx, Wo, bo, attn, MR, DM, DM);

    // residual + LN1
    add_ln_kernel<<<MR, 256>>>(x, attn, g1, be1, x1);

    // FFN
    sgemm_bias<1><<<gFF, 256>>>(x1, W1, b1, hid, MR, FF, DM);
    sgemm_bias<0><<<gDM, 256>>>(hid, W2, b2, ffn, MR, DM, FF);

    // residual + LN2 -> output
    add_ln_kernel<<<MR, 256>>>(x1, ffn, g2, be2, out);
}

// round 12
// speedup vs baseline: 1.3828x; 1.3828x over previous
#include <cuda_runtime.h>
#include <math.h>

// Problem constants
#define BB   4
#define SS   2048
#define DM   1024
#define NH   16
#define HD   64
#define FF   4096
#define MR   (BB*SS)        // 8192 rows
#define QKVD (3*DM)         // 3072

// ---------------------------------------------------------------------------
// Scratch (static __device__ arrays: allocation-free per harness rules)
// ---------------------------------------------------------------------------
__device__ float g_wqkv[DM * QKVD];   // packed [K=1024][3072] weights
__device__ float g_bqkv[QKVD];
__device__ float g_qkv [MR * QKVD];   // fused QKV output
__device__ float g_ctx [MR * DM];
__device__ float g_attn[MR * DM];
__device__ float g_x1  [MR * DM];
__device__ float g_hid [MR * FF];
__device__ float g_ffn [MR * DM];

// ---------------------------------------------------------------------------
// Pack Wq|Wk|Wv into one [1024 x 3072] matrix (and biases). Trivial traffic.
// ---------------------------------------------------------------------------
__global__ void pack_qkv(const float* __restrict__ Wq, const float* __restrict__ Wk,
                         const float* __restrict__ Wv, const float* __restrict__ bq,
                         const float* __restrict__ bk, const float* __restrict__ bv,
                         float* __restrict__ W, float* __restrict__ bias)
{
    int idx = blockIdx.x * blockDim.x + threadIdx.x;
    if (idx < DM * DM) {
        int r = idx >> 10, c = idx & 1023;
        size_t o = (size_t)r * QKVD + c;
        W[o]          = Wq[idx];
        W[o + DM]     = Wk[idx];
        W[o + 2 * DM] = Wv[idx];
    }
    if (idx < DM) {
        bias[idx]          = bq[idx];
        bias[idx + DM]     = bk[idx];
        bias[idx + 2 * DM] = bv[idx];
    }
}

// fast tanh-GELU: tanh(y) = 1 - 2/(exp(2y)+1), MUFU-based
__device__ __forceinline__ float gelu_fast(float t)
{
    float y = 0.7978845608f * (t + 0.044715f * t * t * t);
    float th = 1.f - __fdividef(2.f, __expf(2.f * y) + 1.f);
    return 0.5f * t * (1.f + th);
}

// round fp32 -> tf32 (rna)
__device__ __forceinline__ float tf32r(float x)
{
    float y;
    asm("cvt.rna.tf32.f32 %0, %1;" : "=f"(y) : "f"(x));
    return y;
}

// mma.sync m16n8k8 tf32: c += a * b
__device__ __forceinline__ void mma_tf32(float* c, const float* a, const float* b)
{
    asm volatile(
        "mma.sync.aligned.m16n8k8.row.col.f32.tf32.tf32.f32 "
        "{%0,%1,%2,%3}, {%4,%5,%6,%7}, {%8,%9}, {%0,%1,%2,%3};\n"
        : "+f"(c[0]), "+f"(c[1]), "+f"(c[2]), "+f"(c[3])
        : "r"(__float_as_uint(a[0])), "r"(__float_as_uint(a[1])),
          "r"(__float_as_uint(a[2])), "r"(__float_as_uint(a[3])),
          "r"(__float_as_uint(b[0])), "r"(__float_as_uint(b[1])));
}

// ---------------------------------------------------------------------------
// TF32 tensor-core GEMM: C[M,N] = act(A[M,K] @ B[K,N] + bias[N])
// 128x128 block, BK=16, 256 thr = 8 warps in 2(M)x4(N); warp tile 64x32
// = 4x4 m16n8k8 fragments. Inputs rounded to tf32 at smem staging.
// Smem row stride 136 floats -> fragment LDS conflict-free / <=2-way.
// Double-buffered, one barrier per K-tile (same protocol as fp32 version).
// ---------------------------------------------------------------------------
template<int ACT>
__global__ __launch_bounds__(256)
void sgemm_tc(const float* __restrict__ A, const float* __restrict__ B,
              const float* __restrict__ bias, float* __restrict__ C,
              int M, int N, int K)
{
    __shared__ __align__(16) float As[2][16][136];   // [k][m]
    __shared__ __align__(16) float Bs[2][16][136];   // [k][n]

    const int tid  = threadIdx.x;
    const int bm   = blockIdx.y * 128;
    const int bn   = blockIdx.x * 128;
    const int lane = tid & 31;
    const int wid  = tid >> 5;
    const int gid  = lane >> 2;          // 0..7
    const int ctg  = lane & 3;           // 0..3
    const int wm   = (wid >> 2) * 64;    // warp M offset: 0,64
    const int wn   = (wid & 3) * 32;     // warp N offset: 0,32,64,96

    // staging coords
    const int arow = tid >> 1;           // 0..127
    const int acol = (tid & 1) * 8;      // 0 or 8
    const int brow = wid;                // 0..7 (and +8)
    const int bcol = lane * 4;           // 0..124

    const float* Ap = A + (size_t)(bm + arow) * K + acol;
    const float* Bp = B + (size_t)brow * N + bn + bcol;

    float acc[4][4][4];
#pragma unroll
    for (int mt = 0; mt < 4; mt++)
#pragma unroll
        for (int nt = 0; nt < 4; nt++)
#pragma unroll
            for (int e = 0; e < 4; e++) acc[mt][nt][e] = 0.f;

    // load tile 0 into buffer 0 (tf32-rounded at store)
    float4 av0 = *(const float4*)Ap;
    float4 av1 = *(const float4*)(Ap + 4);
    float4 bv0 = *(const float4*)Bp;
    float4 bv1 = *(const float4*)(Bp + (size_t)8 * N);
    As[0][acol + 0][arow] = tf32r(av0.x);  As[0][acol + 1][arow] = tf32r(av0.y);
    As[0][acol + 2][arow] = tf32r(av0.z);  As[0][acol + 3][arow] = tf32r(av0.w);
    As[0][acol + 4][arow] = tf32r(av1.x);  As[0][acol + 5][arow] = tf32r(av1.y);
    As[0][acol + 6][arow] = tf32r(av1.z);  As[0][acol + 7][arow] = tf32r(av1.w);
    *(float4*)&Bs[0][brow][bcol] =
        make_float4(tf32r(bv0.x), tf32r(bv0.y), tf32r(bv0.z), tf32r(bv0.w));
    *(float4*)&Bs[0][brow + 8][bcol] =
        make_float4(tf32r(bv1.x), tf32r(bv1.y), tf32r(bv1.z), tf32r(bv1.w));
    __syncthreads();

    int buf = 0;
    for (int k0 = 0; k0 < K; k0 += 16) {
        const bool has_next = (k0 + 16 < K);
        if (has_next) {          // prefetch next tile into registers
            Ap += 16;
            Bp += (size_t)16 * N;
            av0 = *(const float4*)Ap;
            av1 = *(const float4*)(Ap + 4);
            bv0 = *(const float4*)Bp;
            bv1 = *(const float4*)(Bp + (size_t)8 * N);
        }

#pragma unroll
        for (int s = 0; s < 2; s++) {
            const int ks = s * 8;
            float af[4][4], bf[4][2];
#pragma unroll
            for (int mt = 0; mt < 4; mt++) {
                const int mr = wm + mt * 16 + gid;
                af[mt][0] = As[buf][ks + ctg][mr];
                af[mt][1] = As[buf][ks + ctg][mr + 8];
                af[mt][2] = As[buf][ks + ctg + 4][mr];
                af[mt][3] = As[buf][ks + ctg + 4][mr + 8];
            }
#pragma unroll
            for (int nt = 0; nt < 4; nt++) {
                const int nc = wn + nt * 8 + gid;
                bf[nt][0] = Bs[buf][ks + ctg][nc];
                bf[nt][1] = Bs[buf][ks + ctg + 4][nc];
            }
#pragma unroll
            for (int mt = 0; mt < 4; mt++)
#pragma unroll
                for (int nt = 0; nt < 4; nt++)
                    mma_tf32(acc[mt][nt], af[mt], bf[nt]);
        }

        if (has_next) {          // store prefetched tile to the idle buffer
            const int nb = buf ^ 1;
            As[nb][acol + 0][arow] = tf32r(av0.x);  As[nb][acol + 1][arow] = tf32r(av0.y);
            As[nb][acol + 2][arow] = tf32r(av0.z);  As[nb][acol + 3][arow] = tf32r(av0.w);
            As[nb][acol + 4][arow] = tf32r(av1.x);  As[nb][acol + 5][arow] = tf32r(av1.y);
            As[nb][acol + 6][arow] = tf32r(av1.z);  As[nb][acol + 7][arow] = tf32r(av1.w);
            *(float4*)&Bs[nb][brow][bcol] =
                make_float4(tf32r(bv0.x), tf32r(bv0.y), tf32r(bv0.z), tf32r(bv0.w));
            *(float4*)&Bs[nb][brow + 8][bcol] =
                make_float4(tf32r(bv1.x), tf32r(bv1.y), tf32r(bv1.z), tf32r(bv1.w));
            __syncthreads();
            buf = nb;
        }
    }

    // epilogue: bias (+ GELU), float2 stores (c = even column)
#pragma unroll
    for (int nt = 0; nt < 4; nt++) {
        const int c = bn + wn + nt * 8 + 2 * ctg;
        const float b0v = bias[c], b1v = bias[c + 1];
#pragma unroll
        for (int mt = 0; mt < 4; mt++) {
            const int r0 = bm + wm + mt * 16 + gid;
            float u0 = acc[mt][nt][0] + b0v;
            float u1 = acc[mt][nt][1] + b1v;
            float u2 = acc[mt][nt][2] + b0v;
            float u3 = acc[mt][nt][3] + b1v;
            if (ACT == 1) {
                u0 = gelu_fast(u0); u1 = gelu_fast(u1);
                u2 = gelu_fast(u2); u3 = gelu_fast(u3);
            }
            *(float2*)&C[(size_t)r0 * N + c]       = make_float2(u0, u1);
            *(float2*)&C[(size_t)(r0 + 8) * N + c] = make_float2(u2, u3);
        }
    }
}

// ---------------------------------------------------------------------------
// Flash attention: per (b, h, q-tile of 64), streaming 32-key tiles.
// DOUBLE-BUFFERED K/V. K stored TRANSPOSED: Kt[d][row], row stride 36 floats
// (144B = 9*16B) so &Kt[d][sk] is 16B-aligned -> LDS.128 in score phase.
// Barriers per iter: A (WAR on buf^1) / C (Ps + stores visible) / D (probs).
// ---------------------------------------------------------------------------
__global__ __launch_bounds__(256)
void attn_kernel(const float* __restrict__ QKV, const unsigned char* __restrict__ mask,
                 float* __restrict__ O)
{
    __shared__ __align__(16) float Qs[64][68];      // f4-aligned rows
    __shared__ __align__(16) float Kt[2][64][36];   // TRANSPOSED: [dim][row]
    __shared__ __align__(16) float Vs[2][32][68];
    __shared__ __align__(16) float Ps[64][36];

    const int tid = threadIdx.x;
    const int q0  = blockIdx.x * 64;
    const int h   = blockIdx.y;
    const int b   = blockIdx.z;

    const size_t rowb  = (size_t)b * SS;
    const size_t qbase = rowb * QKVD + (size_t)h * HD;
    const size_t kbase = qbase + DM;
    const size_t vbase = qbase + 2 * DM;
    const size_t obase = rowb * DM + (size_t)h * HD;
    const unsigned char* mb = mask + (size_t)b * SS * SS;

    // load Q tile (scaled by rsqrt(HD) = 0.125)
    for (int i = tid; i < 64 * 16; i += 256) {
        int r = i >> 4, c = (i & 15) << 2;
        float4 t = *(const float4*)&QKV[qbase + (size_t)(q0 + r) * QKVD + c];
        Qs[r][c]     = t.x * 0.125f;
        Qs[r][c + 1] = t.y * 0.125f;
        Qs[r][c + 2] = t.z * 0.125f;
        Qs[r][c + 3] = t.w * 0.125f;
    }

    // prologue: tile 0 into buffer 0 (K transposed on store)
    for (int p = 0; p < 8; p++) {
        int i = tid + 256 * p, r = i >> 6, c = i & 63;
        Kt[0][c][r] = QKV[kbase + (size_t)r * QKVD + c];
    }
    for (int p = 0; p < 2; p++) {
        int i = tid + 256 * p, r = i >> 4, c = (i & 15) << 2;
        *(float4*)&Vs[0][r][c] = *(const float4*)&QKV[vbase + (size_t)r * QKVD + c];
    }

    // score phase mapping: 2 rows x 4 cols per thread
    const int sq = (tid >> 3) << 1;   // 0,2,..,62
    const int sk = (tid & 7)  << 2;   // 0,4,..,28
    // softmax/acc mapping: 4 threads per row
    const int qi = tid >> 2;          // 0..63
    const int dg = (tid & 3) << 4;    // dim group of 16
    const int c0 = (tid & 3) << 3;    // softmax col group of 8

    float m_i = -1e30f, l_i = 0.f;
    float acc[16];
#pragma unroll
    for (int i = 0; i < 16; i++) acc[i] = 0.f;

    int buf = 0;
    for (int kt = 0; kt < SS; kt += 32) {
        const bool has_next = (kt + 32 < SS);

        // prefetch next K/V tile into registers (latency hidden by A + scores)
        float kreg[8];
        float4 vreg[2];
        if (has_next) {
#pragma unroll
            for (int p = 0; p < 8; p++) {
                int i = tid + 256 * p, r = i >> 6, c = i & 63;
                kreg[p] = QKV[kbase + (size_t)(kt + 32 + r) * QKVD + c];
            }
#pragma unroll
            for (int p = 0; p < 2; p++) {
                int i = tid + 256 * p, r = i >> 4, c = (i & 15) << 2;
                vreg[p] = *(const float4*)&QKV[vbase + (size_t)(kt + 32 + r) * QKVD + c];
            }
        }

        __syncthreads();   // A: prev readers of buf^1 done; current buf visible

        // scores: 2x4 dots of length 64; Q and K both via LDS.128
        float s00 = 0.f, s01 = 0.f, s02 = 0.f, s03 = 0.f;
        float s10 = 0.f, s11 = 0.f, s12 = 0.f, s13 = 0.f;
#pragma unroll
        for (int d = 0; d < 64; d += 4) {
            float qa[4], qb[4];
            float k0[4], k1[4], k2[4], k3[4];   // k_e[y] = K[sk+y][d+e]
            *(float4*)qa = *(const float4*)&Qs[sq][d];
            *(float4*)qb = *(const float4*)&Qs[sq + 1][d];
            *(float4*)k0 = *(const float4*)&Kt[buf][d + 0][sk];
            *(float4*)k1 = *(const float4*)&Kt[buf][d + 1][sk];
            *(float4*)k2 = *(const float4*)&Kt[buf][d + 2][sk];
            *(float4*)k3 = *(const float4*)&Kt[buf][d + 3][sk];
            s00 += qa[0]*k0[0] + qa[1]*k1[0] + qa[2]*k2[0] + qa[3]*k3[0];
            s01 += qa[0]*k0[1] + qa[1]*k1[1] + qa[2]*k2[1] + qa[3]*k3[1];
            s02 += qa[0]*k0[2] + qa[1]*k1[2] + qa[2]*k2[2] + qa[3]*k3[2];
            s03 += qa[0]*k0[3] + qa[1]*k1[3] + qa[2]*k2[3] + qa[3]*k3[3];
            s10 += qb[0]*k0[0] + qb[1]*k1[0] + qb[2]*k2[0] + qb[3]*k3[0];
            s11 += qb[0]*k0[1] + qb[1]*k1[1] + qb[2]*k2[1] + qb[3]*k3[1];
            s12 += qb[0]*k0[2] + qb[1]*k1[2] + qb[2]*k2[2] + qb[3]*k3[2];
            s13 += qb[0]*k0[3] + qb[1]*k1[3] + qb[2]*k2[3] + qb[3]*k3[3];
        }
        // mask (all-False in this problem's inputs; kept for robustness)
        {
            const unsigned char* m0 = mb + (size_t)(q0 + sq) * SS + kt + sk;
            const unsigned char* m1 = m0 + SS;
            if (m0[0]) s00 = -1e30f; if (m0[1]) s01 = -1e30f;
            if (m0[2]) s02 = -1e30f; if (m0[3]) s03 = -1e30f;
            if (m1[0]) s10 = -1e30f; if (m1[1]) s11 = -1e30f;
            if (m1[2]) s12 = -1e30f; if (m1[3]) s13 = -1e30f;
        }
        Ps[sq][sk] = s00; Ps[sq][sk + 1] = s01; Ps[sq][sk + 2] = s02; Ps[sq][sk + 3] = s03;
        Ps[sq + 1][sk] = s10; Ps[sq + 1][sk + 1] = s11;
        Ps[sq + 1][sk + 2] = s12; Ps[sq + 1][sk + 3] = s13;

        // store prefetched tile into the idle buffer (K transposed)
        if (has_next) {
            const int nb = buf ^ 1;
#pragma unroll
            for (int p = 0; p < 8; p++) {
                int i = tid + 256 * p, r = i >> 6, c = i & 63;
                Kt[nb][c][r] = kreg[p];
            }
#pragma unroll
            for (int p = 0; p < 2; p++) {
                int i = tid + 256 * p, r = i >> 4, c = (i & 15) << 2;
                *(float4*)&Vs[nb][r][c] = vreg[p];
            }
        }

        __syncthreads();   // C: Ps scores visible; buf^1 stores ordered

        // online softmax: 4 threads per row, 8 cols each
        float pv[8];
        float rmax = -1e30f;
#pragma unroll
        for (int j = 0; j < 8; j++) { pv[j] = Ps[qi][c0 + j]; rmax = fmaxf(rmax, pv[j]); }
        rmax = fmaxf(rmax, __shfl_xor_sync(0xffffffffu, rmax, 1));
        rmax = fmaxf(rmax, __shfl_xor_sync(0xffffffffu, rmax, 2));
        float m_new = fmaxf(m_i, rmax);
        float corr  = __expf(m_i - m_new);
        float psum  = 0.f;
#pragma unroll
        for (int j = 0; j < 8; j++) {
            pv[j] = __expf(pv[j] - m_new);
            psum += pv[j];
            Ps[qi][c0 + j] = pv[j];
        }
        psum += __shfl_xor_sync(0xffffffffu, psum, 1);
        psum += __shfl_xor_sync(0xffffffffu, psum, 2);
        l_i = l_i * corr + psum;
        m_i = m_new;
#pragma unroll
        for (int i = 0; i < 16; i++) acc[i] *= corr;

        __syncthreads();   // D: Ps probabilities visible to whole block

        // acc += P @ V   (thread owns (row qi, 16 dims dg..dg+15)); V via float4 LDS
#pragma unroll 8
        for (int j = 0; j < 32; j++) {
            float p = Ps[qi][j];
            float v0[4], v1[4], v2[4], v3[4];
            *(float4*)v0 = *(const float4*)&Vs[buf][j][dg];
            *(float4*)v1 = *(const float4*)&Vs[buf][j][dg + 4];
            *(float4*)v2 = *(const float4*)&Vs[buf][j][dg + 8];
            *(float4*)v3 = *(const float4*)&Vs[buf][j][dg + 12];
#pragma unroll
            for (int e = 0; e < 4; e++) {
                acc[e]      += p * v0[e];
                acc[4 + e]  += p * v1[e];
                acc[8 + e]  += p * v2[e];
                acc[12 + e] += p * v3[e];
            }
        }

        buf ^= 1;
    }

    const float inv = 1.f / l_i;
#pragma unroll
    for (int i = 0; i < 16; i++)
        O[obase + (size_t)(q0 + qi) * DM + dg + i] = acc[i] * inv;
}

// ---------------------------------------------------------------------------
// out = LayerNorm(A + B) * gamma + beta      (one block per 1024-wide row)
// ---------------------------------------------------------------------------
__global__ __launch_bounds__(256)
void add_ln_kernel(const float* __restrict__ A, const float* __restrict__ Bv,
                   const float* __restrict__ gam, const float* __restrict__ bet,
                   float* __restrict__ out)
{
    __shared__ float red[8];
    const int row = blockIdx.x;
    const int t = threadIdx.x;

    float4 av = ((const float4*)(A  + (size_t)row * DM))[t];
    float4 bv = ((const float4*)(Bv + (size_t)row * DM))[t];
    float v0 = av.x + bv.x, v1 = av.y + bv.y, v2 = av.z + bv.z, v3 = av.w + bv.w;

    float s = v0 + v1 + v2 + v3;
#pragma unroll
    for (int o = 16; o > 0; o >>= 1) s += __shfl_xor_sync(0xffffffffu, s, o);
    if ((t & 31) == 0) red[t >> 5] = s;
    __syncthreads();
    float mu = 0.f;
#pragma unroll
    for (int i = 0; i < 8; i++) mu += red[i];
    mu *= (1.f / 1024.f);
    __syncthreads();

    float d0 = v0 - mu, d1 = v1 - mu, d2 = v2 - mu, d3 = v3 - mu;
    float sv = d0 * d0 + d1 * d1 + d2 * d2 + d3 * d3;
#pragma unroll
    for (int o = 16; o > 0; o >>= 1) sv += __shfl_xor_sync(0xffffffffu, sv, o);
    if ((t & 31) == 0) red[t >> 5] = sv;
    __syncthreads();
    float var = 0.f;
#pragma unroll
    for (int i = 0; i < 8; i++) var += red[i];
    var *= (1.f / 1024.f);
    const float inv = rsqrtf(var + 1e-5f);

    float4 g4 = ((const float4*)gam)[t];
    float4 e4 = ((const float4*)bet)[t];
    float4 o4;
    o4.x = d0 * inv * g4.x + e4.x;
    o4.y = d1 * inv * g4.y + e4.y;
    o4.z = d2 * inv * g4.z + e4.z;
    o4.w = d3 * inv * g4.w + e4.w;
    ((float4*)(out + (size_t)row * DM))[t] = o4;
}

// ---------------------------------------------------------------------------
// Launch
// ---------------------------------------------------------------------------
extern "C" void kernel_launch(void* const* d_in, const int* in_sizes, int n_in,
                              void* d_out, int out_size)
{
    const float* x  = (const float*)d_in[0];
    const unsigned char* mask = (const unsigned char*)d_in[1];
    const float* Wq = (const float*)d_in[2];
    const float* bq = (const float*)d_in[3];
    const float* Wk = (const float*)d_in[4];
    const float* bk = (const float*)d_in[5];
    const float* Wv = (const float*)d_in[6];
    const float* bv = (const float*)d_in[7];
    const float* Wo = (const float*)d_in[8];
    const float* bo = (const float*)d_in[9];
    const float* g1 = (const float*)d_in[10];
    const float* be1= (const float*)d_in[11];
    const float* W1 = (const float*)d_in[12];
    const float* b1 = (const float*)d_in[13];
    const float* W2 = (const float*)d_in[14];
    const float* b2 = (const float*)d_in[15];
    const float* g2 = (const float*)d_in[16];
    const float* be2= (const float*)d_in[17];
    float* out = (float*)d_out;

    float *wqkv, *bqkv, *qkv, *ctx, *attn, *x1, *hid, *ffn;
    cudaGetSymbolAddress((void**)&wqkv, g_wqkv);
    cudaGetSymbolAddress((void**)&bqkv, g_bqkv);
    cudaGetSymbolAddress((void**)&qkv,  g_qkv);
    cudaGetSymbolAddress((void**)&ctx,  g_ctx);
    cudaGetSymbolAddress((void**)&attn, g_attn);
    cudaGetSymbolAddress((void**)&x1,   g_x1);
    cudaGetSymbolAddress((void**)&hid,  g_hid);
    cudaGetSymbolAddress((void**)&ffn,  g_ffn);

    // pack QKV weights, then one fused projection GEMM
    pack_qkv<<<(DM * DM + 255) / 256, 256>>>(Wq, Wk, Wv, bq, bk, bv, wqkv, bqkv);

    const dim3 gQKV(QKVD / 128, MR / 128);  // (24, 64)
    const dim3 gDM (DM   / 128, MR / 128);  // (8, 64)
    const dim3 gFF (FF   / 128, MR / 128);  // (32, 64)

    sgemm_tc<0><<<gQKV, 256>>>(x, wqkv, bqkv, qkv, MR, QKVD, DM);

    // attention
    attn_kernel<<<dim3(SS / 64, NH, BB), 256>>>(qkv, mask, ctx);

    // output projection
    sgemm_tc<0><<<gDM, 256>>>(ctx, Wo, bo, attn, MR, DM, DM);

    // residual + LN1
    add_ln_kernel<<<MR, 256>>>(x, attn, g1, be1, x1);

    // FFN
    sgemm_tc<1><<<gFF, 256>>>(x1, W1, b1, hid, MR, FF, DM);
    sgemm_tc<0><<<gDM, 256>>>(hid, W2, b2, ffn, MR, DM, FF);

    // residual + LN2 -> output
    add_ln_kernel<<<MR, 256>>>(x1, ffn, g2, be2, out);
}